// round 16
// baseline (speedup 1.0000x reference)
#include <cuda_runtime.h>
#include <cuda_bf16.h>
#include <stdint.h>

// Problem constants: shape (16, 1, 320, 320) fp32, two tensors (pred, target)
#define NIMG   16
#define H      320
#define W      320
#define W2     160             // pixel-pairs per row
#define WPR    10              // 32-bit words per row (320/32)
#define NPIX   (NIMG * H * W)  // 1,638,400
#define NROWS  (NIMG * H)      // 5,120
#define SENT   0x7FFF
#define SENT2  (SENT * SENT)
#define CAPQ   0x3FFF          // saturation cap for stored squared distances
#define BIGF   1e12f
#define SW     2               // strip width in pairs (4 pixels)
#define NSTRIP (W2 / SW)       // 80 strips per image
#define NB2    (NIMG * NSTRIP) // 1280 k_loss blocks
#define TPAIRS (H * SW)        // 640 pairs per strip tile

// Scratch (static device globals — no allocation).
// g_Dsq [p]: per tensor halfword: class<<15 | min(horizDistToOpp^2, CAPQ)
// g_bits    : packed (v>0.5) bits, [tensor][row][word] (cold-path source)
__device__ __align__(256) uint32_t g_Dsq[NPIX];
__device__ __align__(256) uint32_t g_bits[2 * NROWS * WPR];
__device__ double       g_part[NB2];
__device__ unsigned int g_ticket = 0;    // self-resetting via atomicInc wrap

// ---------------------------------------------------------------------------
// Exact horizontal distance to nearest opposite-class bit; branchless 64-bit
// window covers d<=32 (overwhelmingly common), rare multi-word scan fallback.
__device__ __forceinline__ int nearest_dist64(const uint32_t* wr, int j, int L,
                                              uint32_t pol) {
    uint32_t cj   = wr[j] ^ pol;
    uint32_t cjm1 = (j > 0)       ? (wr[j - 1] ^ pol) : 0u;
    uint32_t cjp1 = (j < WPR - 1) ? (wr[j + 1] ^ pol) : 0u;

    uint64_t winL = ((uint64_t)cj << 32) | cjm1;
    int pos = 32 + L;
    uint64_t mlow = winL & ((2ull << pos) - 1ull);
    int dl;
    if (mlow) {
        dl = pos - 63 + __clzll((long long)mlow);
    } else {
        dl = SENT;
        for (int k2 = j - 2; k2 >= 0; --k2) {          // rare
            uint32_t mm = wr[k2] ^ pol;
            if (mm) { dl = j * 32 + L - (k2 * 32 + 31 - __clz(mm)); break; }
        }
    }
    uint64_t winR = ((uint64_t)cjp1 << 32) | cj;
    uint64_t mhigh = winR & (~0ull << L);
    int dr;
    if (mhigh) {
        dr = __ffsll((long long)mhigh) - 1 - L;
    } else {
        dr = SENT;
        for (int k2 = j + 2; k2 < WPR; ++k2) {         // rare
            uint32_t mm = wr[k2] ^ pol;
            if (mm) { dr = k2 * 32 + (__ffs(mm) - 1) - (j * 32 + L); break; }
        }
    }
    return min(min(dl, dr), SENT);
}

// ---------------------------------------------------------------------------
// COLD exact path: nearest opposite-class bit in one bit-row (full scan).
__device__ int exact_d1(const uint32_t* rb, int x, uint32_t pol) {
    int best = SENT;
    for (int j = 0; j < WPR; ++j) {
        uint32_t m = rb[j] ^ pol;
        while (m) {
            int b = __ffs(m) - 1;
            int pos = j * 32 + b;
            best = min(best, abs(pos - x));
            m &= m - 1;
        }
    }
    return best;
}

// COLD exact per-pixel fallback (only when the SIMD result may have
// saturated, i.e. true field value might exceed CAPQ). Recomputes from bits.
__device__ __noinline__ float fallback_pixel(int pix, int y) {
    int rowg = pix / W;
    int x = pix - rowg * W;
    float res = 0.f;
#pragma unroll
    for (int t = 0; t < 2; ++t) {
        const uint32_t* rb = g_bits + (t * NROWS + rowg) * WPR;
        uint32_t c = (rb[x >> 5] >> (x & 31)) & 1u;
        uint32_t pol = c ? 0xFFFFFFFFu : 0u;
        int d0 = exact_d1(rb, x, pol);
        int best = (d0 >= SENT) ? SENT2 : d0 * d0;
        for (int dy = 1; dy < H; ++dy) {
            int dy2 = dy * dy;
            if (dy2 >= best) break;
            if (y - dy >= 0) {
                int d = exact_d1(rb - dy * WPR, x, pol);
                if (d < SENT) best = min(best, dy2 + d * d);
            }
            if (y + dy < H) {
                int d = exact_d1(rb + dy * WPR, x, pol);
                if (d < SENT) best = min(best, dy2 + d * d);
            }
        }
        // best>=SENT2 <=> no opposite-class pixel in the image:
        //   fg pixel -> field^2 = BIG ; bg pixel -> reference zeroes -> 0
        res += (best >= SENT2) ? (c ? BIGF : 0.f) : (float)best;
    }
    return res;
}

// ---------------------------------------------------------------------------
// Kernel 1: horizontal pass, one row per warp. 640 blocks x 256.
__global__ void __launch_bounds__(256) k_rows(const float* __restrict__ pred,
                                              const float* __restrict__ targ) {
    const int tid  = threadIdx.x;
    const int warp = tid >> 5;
    const int L    = tid & 31;
    __shared__ uint32_t srow[8][2][WPR];

    int row = blockIdx.x * 8 + warp;        // 640*8 = 5120 rows exact
    int base = row * W;
    uint32_t* sp = &srow[warp][0][0];
    uint32_t* st = &srow[warp][1][0];
    for (int j = 0; j < WPR; ++j) {
        float p  = pred[base + j * 32 + L];
        float tt = targ[base + j * 32 + L];
        uint32_t bp = __ballot_sync(0xFFFFFFFFu, p > 0.5f);
        uint32_t bt = __ballot_sync(0xFFFFFFFFu, tt > 0.5f);
        if (L == 0) { sp[j] = bp; st[j] = bt; }
    }
    __syncwarp();
    // persist bit-rows for the cold exact fallback
    if (L < WPR) {
        g_bits[(0 * NROWS + row) * WPR + L] = sp[L];
        g_bits[(1 * NROWS + row) * WPR + L] = st[L];
    }
    for (int j = 0; j < WPR; ++j) {
        uint32_t c0 = (sp[j] >> L) & 1u;
        uint32_t c1 = (st[j] >> L) & 1u;
        int d0 = nearest_dist64(sp, j, L, c0 ? 0xFFFFFFFFu : 0u);
        int d1 = nearest_dist64(st, j, L, c1 ? 0xFFFFFFFFu : 0u);
        uint32_t q0 = (c0 << 15) | (uint32_t)min(d0 * d0, CAPQ);
        uint32_t q1 = (c1 << 15) | (uint32_t)min(d1 * d1, CAPQ);
        g_Dsq[base + j * 32 + L] = q0 | (q1 << 16);
    }
}

// ---------------------------------------------------------------------------
// Kernel 2: smem column-strip vertical pass + loss + ticketed final reduce.
// 1280 blocks x 256 threads; strip = full height x 2 pairs (4 pixels).
// 8 blocks/SM = 2048 threads = full occupancy (fixes wave quantization).
__global__ void __launch_bounds__(256) k_loss(const float* __restrict__ pred,
                                              const float* __restrict__ targ,
                                              float* __restrict__ out) {
    const int tid = threadIdx.x;
    const int bid = blockIdx.x;
    const int img   = bid / NSTRIP;
    const int strip = bid - img * NSTRIP;
    const uint2* DQ = (const uint2*)g_Dsq;
    const int gbase = img * H * W2 + strip * SW;

    __shared__ uint2 tile[TPAIRS];          // 5.1 KB
    for (int idx = tid; idx < TPAIRS; idx += 256) {
        tile[idx] = DQ[gbase + (idx >> 1) * W2 + (idx & 1)];
    }
    __syncthreads();

    float fsum = 0.f;
#pragma unroll
    for (int k = 0; k < 3; ++k) {           // 640 pairs, 256 threads: 2.5/thread
        int idx = k * 256 + tid;
        if (idx >= TPAIRS) break;           // only the 3rd iteration is partial
        int y  = idx >> 1;
        int yd = (H - 1) - y;

        uint2 own = tile[idx];
        uint32_t mx = own.x & 0x80008000u;           // query class masks
        uint32_t my = own.y & 0x80008000u;
        uint32_t bx = __vmaxs2(own.x ^ mx, 0u);      // own sat d^2 (<= CAPQ)
        uint32_t by = __vmaxs2(own.y ^ my, 0u);

        // Straight-line dy=1..4 with CLAMPED indices (no branches). Clamped
        // reads re-read row 0/H-1 with larger dy^2 than their true term
        // (already covered at dy=y / dy=yd) => never lowers best below the
        // true minimum.
#pragma unroll
        for (int dy = 1; dy <= 4; ++dy) {
            int du = min(dy, y);
            int dd = min(dy, yd);
            uint2 vu = tile[idx - du * SW];
            uint2 vd = tile[idx + dd * SW];
            uint32_t dp = (uint32_t)(dy * dy) * 0x00010001u;
            bx = __vmins2(bx, __vadd2(__vmaxs2(vu.x ^ mx, 0u), dp));
            by = __vmins2(by, __vadd2(__vmaxs2(vu.y ^ my, 0u), dp));
            bx = __vmins2(bx, __vadd2(__vmaxs2(vd.x ^ mx, 0u), dp));
            by = __vmins2(by, __vadd2(__vmaxs2(vd.y ^ my, 0u), dp));
        }

        // Rare tail: 2-dy chunks with shrink checks; dy<=127 => s16 adds
        // can't overflow (127^2 + CAPQ = 32512 < 32768).
        uint32_t m2 = __vmaxs2(bx, by);
        int bb = max((int)(m2 >> 16), (int)(m2 & 0xFFFFu));
        for (int dy = 5; dy <= 127 && dy * dy < bb; dy += 2) {
            int dya = dy, dyb = dy + 1;
            uint32_t dpa = (uint32_t)(dya * dya) * 0x00010001u;
            uint32_t dpb = (uint32_t)(dyb * dyb) * 0x00010001u;
            uint2 vua = tile[idx - min(dya, y) * SW];
            uint2 vda = tile[idx + min(dya, yd) * SW];
            uint2 vub = tile[idx - min(dyb, y) * SW];
            uint2 vdb = tile[idx + min(dyb, yd) * SW];
            bx = __vmins2(bx, __vadd2(__vmaxs2(vua.x ^ mx, 0u), dpa));
            by = __vmins2(by, __vadd2(__vmaxs2(vua.y ^ my, 0u), dpa));
            bx = __vmins2(bx, __vadd2(__vmaxs2(vda.x ^ mx, 0u), dpa));
            by = __vmins2(by, __vadd2(__vmaxs2(vda.y ^ my, 0u), dpa));
            bx = __vmins2(bx, __vadd2(__vmaxs2(vub.x ^ mx, 0u), dpb));
            by = __vmins2(by, __vadd2(__vmaxs2(vub.y ^ my, 0u), dpb));
            bx = __vmins2(bx, __vadd2(__vmaxs2(vdb.x ^ mx, 0u), dpb));
            by = __vmins2(by, __vadd2(__vmaxs2(vdb.y ^ my, 0u), dpb));
            m2 = __vmaxs2(bx, by);
            bb = max((int)(m2 >> 16), (int)(m2 & 0xFFFFu));
        }

        int b00 = (int)(bx & 0xFFFFu), b01 = (int)(bx >> 16);
        int b10 = (int)(by & 0xFFFFu), b11 = (int)(by >> 16);

        int gp = gbase + y * W2 + (idx & 1);         // global pair index
        float2 pv = ((const float2*)pred)[gp];
        float2 tv = ((const float2*)targ)[gp];
        float e0 = pv.x - tv.x;
        float e1 = pv.y - tv.y;
        // >= CAPQ => may involve saturation or the dy cap -> exact recompute
        float f0 = (max(b00, b01) >= CAPQ) ? fallback_pixel(2 * gp, y)
                                           : (float)(b00 + b01);
        float f1 = (max(b10, b11) >= CAPQ) ? fallback_pixel(2 * gp + 1, y)
                                           : (float)(b10 + b11);
        fsum += e0 * e0 * f0 + e1 * e1 * f1;
    }

    // block reduce (8 warps) -> double partial
#pragma unroll
    for (int off = 16; off; off >>= 1)
        fsum += __shfl_down_sync(0xFFFFFFFFu, fsum, off);
    __shared__ float ws[8];
    if ((tid & 31) == 0) ws[tid >> 5] = fsum;
    __syncthreads();
    __shared__ bool isLast;
    if (tid == 0) {
        float v = ws[0];
#pragma unroll
        for (int k = 1; k < 8; ++k) v += ws[k];
        g_part[bid] = (double)v;
        __threadfence();
        unsigned int tk = atomicInc(&g_ticket, NB2 - 1);  // wraps to 0 => self-reset
        isLast = (tk == NB2 - 1);
    }
    __syncthreads();

    if (isLast) {
        double acc = 0.0;
        for (int k = tid; k < NB2; k += 256) acc += g_part[k];
#pragma unroll
        for (int off = 16; off; off >>= 1)
            acc += __shfl_down_sync(0xFFFFFFFFu, acc, off);
        __shared__ double wd[8];
        if ((tid & 31) == 0) wd[tid >> 5] = acc;
        __syncthreads();
        if (tid == 0) {
            double s = wd[0];
#pragma unroll
            for (int k = 1; k < 8; ++k) s += wd[k];
            out[0] = (float)(s / (double)NPIX);
        }
    }
}

// ---------------------------------------------------------------------------
extern "C" void kernel_launch(void* const* d_in, const int* in_sizes, int n_in,
                              void* d_out, int out_size) {
    const float* pred = (const float*)d_in[0];
    const float* targ = (const float*)d_in[1];
    float* out = (float*)d_out;

    k_rows<<<640, 256>>>(pred, targ);
    k_loss<<<NB2, 256>>>(pred, targ, out);
}